// round 5
// baseline (speedup 1.0000x reference)
#include <cuda_runtime.h>

#define S        48
#define C        32
#define SSS      (S*S*S)          // 110592
#define SLOTS    27               // (i,j) slots per round; 3 rounds * 27 = 81
#define RANGES   12               // d split into 12 ranges of 4
#define NTHREADS 352              // 324 compute/loader threads + pad to 11 warps
#define CCH      4                // channels per chunk
#define NCHUNK   8                // 32 / 4
#define SLOT_STRIDE 80            // floats per (c,slot) row; 80 % 32 == 16 -> LDS.128 conflict-free
#define X2STAGE  (CCH*SLOTS*SLOT_STRIDE)   // 8640 floats per stage
#define X1SZ     (C*S)            // 1536 floats
#define SOFFN    81
#define SMEM_BYTES ((X1SZ + 2*X2STAGE + SOFFN)*4)   // 75,588 bytes

typedef unsigned long long u64;

__device__ __forceinline__ void cp_async16(unsigned dst, const void* src, unsigned sz) {
    asm volatile("cp.async.cg.shared.global [%0], [%1], 16, %2;"
                 :: "r"(dst), "l"(src), "r"(sz) : "memory");
}
__device__ __forceinline__ void cp_commit() {
    asm volatile("cp.async.commit_group;" ::: "memory");
}
template<int N>
__device__ __forceinline__ void cp_wait() {
    asm volatile("cp.async.wait_group %0;" :: "n"(N) : "memory");
}

// ---- packed fp32 helpers (sm_103a dual-FMA path) ----
__device__ __forceinline__ u64 fpack(float lo, float hi) {
    u64 r; asm("mov.b64 %0, {%1, %2};" : "=l"(r) : "f"(lo), "f"(hi)); return r;
}
__device__ __forceinline__ void funpack(u64 v, float& lo, float& hi) {
    asm("mov.b64 {%0, %1}, %2;" : "=f"(lo), "=f"(hi) : "l"(v));
}
__device__ __forceinline__ u64 ffma2(u64 a, u64 b, u64 c) {
    u64 d; asm("fma.rn.f32x2 %0, %1, %2, %3;" : "=l"(d) : "l"(a), "l"(b), "l"(c)); return d;
}
__device__ __forceinline__ u64 fmul2(u64 a, u64 b) {
    u64 d; asm("mul.rn.f32x2 %0, %1, %2;" : "=l"(d) : "l"(a), "l"(b)); return d;
}

// One channel-chunk (4 ch) of all 27 shifted x2 d-columns.
// smem row: bd in [0,56), row[bd] = x2p[bd] = x2[bd-4]. Loader covers bd 4..51;
// fringes bd 0..3 / 52..55 pre-zeroed once per block. OOB slots -> zfill.
// 1296 items = 4 j-iters x 324 threads; t = j*27+q, c = t&3, sl = t>>2.
__device__ __forceinline__ void issue_chunk(
    const float* __restrict__ x2, unsigned x2s_base_u32,
    const int* __restrict__ soffs,
    int rbase, int cc, int stage, int q, int dd, bool loader)
{
    if (loader) {
        const int cbase = cc * CCH;
        const unsigned dstb = x2s_base_u32 + (unsigned)(stage * X2STAGE) * 4u
                                           + (unsigned)(dd + 4) * 4u;
        #pragma unroll
        for (int j = 0; j < 4; ++j) {
            int t  = j * SLOTS + q;     // 0..107
            int c  = t & 3;
            int sl = t >> 2;            // 0..26
            int off = soffs[rbase + sl];
            bool valid = (off >= 0);
            const float* src = x2 + (size_t)(cbase + c) * SSS + (valid ? off + dd : 0);
            unsigned dst = dstb + (unsigned)((c * SLOTS + sl) * SLOT_STRIDE) * 4u;
            cp_async16(dst, src, valid ? 16u : 0u);
        }
    }
    cp_commit();
}

__global__ __launch_bounds__(NTHREADS, 2)
void corr3d_kernel(const float* __restrict__ x1,
                   const float* __restrict__ x2,
                   float* __restrict__ out)
{
    extern __shared__ float smem[];
    float* x1s = smem;                           // [C][48]
    float* x2s = smem + X1SZ;                    // [2][CCH][SLOTS][SLOT_STRIDE]
    int*   soffs = (int*)(smem + X1SZ + 2 * X2STAGE);  // [81]

    const int h   = blockIdx.x;
    const int w   = blockIdx.y;
    const int tid = threadIdx.x;

    const unsigned x2s_base = (unsigned)__cvta_generic_to_shared(x2s);

    // x1 column (32ch x 48d): 384 float4 loads over 352 threads.
    #pragma unroll 1
    for (int t = tid; t < C * 12; t += NTHREADS) {
        int c = t / 12, vq = t % 12;
        const float4* src = (const float4*)(x1 + (((size_t)c * S + h) * S + w) * S) + vq;
        ((float4*)x1s)[c * 12 + vq] = *src;
    }

    // Per-(round,slot) source offsets: off = (hh*S+ww)*S, or -1 if OOB.
    if (tid < SOFFN) {
        int oi = tid / 9, oj = tid - oi * 9;
        int hh = h + oi - 4, ww = w + oj - 4;
        soffs[tid] = (((unsigned)hh < S) && ((unsigned)ww < S)) ? (hh * S + ww) * S : -1;
    }

    // Pre-zero pad fringes (bd 0..3 and 52..55) of both stages.
    {
        float4 z = make_float4(0.f, 0.f, 0.f, 0.f);
        #pragma unroll 1
        for (int it = tid; it < 2 * CCH * SLOTS * 2; it += NTHREADS) {
            int stage = it / (CCH * SLOTS * 2);
            int r     = it - stage * (CCH * SLOTS * 2);
            int row   = r >> 1;             // c*27+sl
            int p     = r & 1;              // 0: bd0..3, 1: bd52..55
            ((float4*)x2s)[(stage * X2STAGE + row * SLOT_STRIDE) / 4 + (p ? 13 : 0)] = z;
        }
    }
    __syncthreads();

    const bool loader = (tid < SLOTS * RANGES);   // 324
    const int  q      = tid / RANGES;             // == slot
    const int  vr     = tid % RANGES;             // == rng
    const int  dd     = vr * 4;
    const int  slot   = q;
    const int  d0     = vr * 4;
    const bool active = loader;
    const u64 inv2 = fpack(1.0f / (float)C, 1.0f / (float)C);

    u64 acc2[18];   // acc2[2k] = out(t0,t1;k), acc2[2k+1] = out(t2,t3;k)

    #pragma unroll 1
    for (int round = 0; round < 3; ++round) {
        const int rbase = round * SLOTS;
        #pragma unroll
        for (int i = 0; i < 18; ++i) acc2[i] = 0ull;

        issue_chunk(x2, x2s_base, soffs, rbase, 0, 0, q, dd, loader);

        #pragma unroll 1
        for (int cc = 0; cc < NCHUNK; ++cc) {
            if (cc < NCHUNK - 1) {
                issue_chunk(x2, x2s_base, soffs, rbase, cc + 1, (cc + 1) & 1, q, dd, loader);
                cp_wait<1>();
            } else {
                cp_wait<0>();
            }
            __syncthreads();

            if (active) {
                const float* xb = x2s + (cc & 1) * X2STAGE;
                const int cg0 = cc * CCH;
                #pragma unroll
                for (int c = 0; c < CCH; ++c) {
                    // x1 pair operands, free from LDS.128 register pairs
                    const ulonglong2 a2 =
                        *(const ulonglong2*)(x1s + (cg0 + c) * S + d0);
                    const u64 av01 = a2.x, av23 = a2.y;

                    const float* wr = xb + (c * SLOTS + slot) * SLOT_STRIDE + d0;
                    const ulonglong2 w0 = *(const ulonglong2*)(wr);      // (0,1)(2,3)
                    const ulonglong2 w1 = *(const ulonglong2*)(wr + 4);  // (4,5)(6,7)
                    const ulonglong2 w2 = *(const ulonglong2*)(wr + 8);  // (8,9)(10,11)
                    u64 ep[6] = {w0.x, w0.y, w1.x, w1.y, w2.x, w2.y};

                    // odd-aligned pairs (wv[2m+1], wv[2m+2]), m = 0..4
                    u64 op[5];
                    #pragma unroll
                    for (int m = 0; m < 5; ++m) {
                        float l0, h0, l1, h1;
                        funpack(ep[m], l0, h0);
                        funpack(ep[m + 1], l1, h1);
                        op[m] = fpack(h0, l1);
                    }

                    // out(d0+t, k) reads wv[k+t]
                    #pragma unroll
                    for (int k = 0; k < 9; ++k) {
                        u64 b01 = (k & 1) ? op[(k - 1) >> 1] : ep[k >> 1];
                        u64 b23 = (k & 1) ? op[(k + 1) >> 1] : ep[(k >> 1) + 1];
                        acc2[2 * k]     = ffma2(av01, b01, acc2[2 * k]);
                        acc2[2 * k + 1] = ffma2(av23, b23, acc2[2 * k + 1]);
                    }
                }
            }
            __syncthreads();
        }

        if (active) {
            const int ij = rbase + slot;          // out channel = ij*9 + k
            float* obase = out + (size_t)ij * 9 * SSS + ((size_t)h * S + w) * S + d0;
            #pragma unroll
            for (int k = 0; k < 9; ++k) {
                ulonglong2 v;
                v.x = fmul2(acc2[2 * k], inv2);
                v.y = fmul2(acc2[2 * k + 1], inv2);
                *(ulonglong2*)(obase + (size_t)k * SSS) = v;
            }
        }
    }
}

extern "C" void kernel_launch(void* const* d_in, const int* in_sizes, int n_in,
                              void* d_out, int out_size)
{
    const float* x1 = (const float*)d_in[0];
    const float* x2 = (const float*)d_in[1];
    float* out = (float*)d_out;

    cudaFuncSetAttribute(corr3d_kernel,
                         cudaFuncAttributeMaxDynamicSharedMemorySize, SMEM_BYTES);
    dim3 grid(S, S);
    corr3d_kernel<<<grid, NTHREADS, SMEM_BYTES>>>(x1, x2, out);
}